// round 8
// baseline (speedup 1.0000x reference)
#include <cuda_runtime.h>
#include <cuda_bf16.h>
#include <cstdint>
#include <math.h>

#define B     64
#define T     256
#define U     1024
#define G3    3072
#define NBLK  128
#define NT    512

// h packed in MMA A-fragment order:
// [par][ (((g*64 + kk)*4) + bt*2 + half)*32 + lane ] -> uint4
//   g = batch group (32 batches), kk = k-tile (64), bt = batch-tile in group (16), half: 0=hi,1=lo
__device__ __align__(16) uint4 g_hpk[2][16384];
__device__ unsigned g_cnt0, g_gen0, g_cnt1, g_gen1;

// ---- SMEM layout (bytes) ----
#define SM_W     0
#define W_NSTR   2064
#define W_PSTR   49536
#define SM_REC0  99072              // float [16 plane][32][26]
#define SM_REC1  152320
#define REC_PL   832                // floats per plane
#define SMEM_TOTAL 205568

// ---- PTX helpers ----
__device__ __forceinline__ uint32_t smem_u32(const void* p) {
    uint32_t a;
    asm("{ .reg .u64 t; cvta.to.shared.u64 t, %1; cvt.u32.u64 %0, t; }" : "=r"(a) : "l"(p));
    return a;
}
__device__ __forceinline__ void ldsm2(uint32_t* r, uint32_t addr) {
    asm volatile("ldmatrix.sync.aligned.m8n8.x2.shared.b16 {%0,%1}, [%2];"
                 : "=r"(r[0]), "=r"(r[1]) : "r"(addr));
}
__device__ __forceinline__ void ldsm4(uint32_t* r, uint32_t addr) {
    asm volatile("ldmatrix.sync.aligned.m8n8.x4.shared.b16 {%0,%1,%2,%3}, [%4];"
                 : "=r"(r[0]), "=r"(r[1]), "=r"(r[2]), "=r"(r[3]) : "r"(addr));
}
__device__ __forceinline__ void mma4(float* c, const uint4& a, uint32_t b0, uint32_t b1) {
    asm volatile("mma.sync.aligned.m16n8k16.row.col.f32.bf16.bf16.f32 "
                 "{%0,%1,%2,%3}, {%4,%5,%6,%7}, {%8,%9}, {%0,%1,%2,%3};"
                 : "+f"(c[0]), "+f"(c[1]), "+f"(c[2]), "+f"(c[3])
                 : "r"(a.x), "r"(a.y), "r"(a.z), "r"(a.w), "r"(b0), "r"(b1));
}
__device__ __forceinline__ void wait_gen(unsigned* gen, unsigned tgt) {
    unsigned g;
    do { asm volatile("ld.acquire.gpu.u32 %0, [%1];" : "=r"(g) : "l"(gen)); }
    while ((int)(g - tgt) < 0);
}
__device__ __forceinline__ void arrive_bar(unsigned* cnt, unsigned* gen) {
    unsigned prev;
    asm volatile("atom.release.gpu.global.add.u32 %0, [%1], 1;" : "=r"(prev) : "l"(cnt));
    if (prev == NBLK - 1) {
        asm volatile("st.relaxed.gpu.global.u32 [%0], 0;" :: "l"(cnt));
        asm volatile("red.release.gpu.global.add.u32 [%0], 1;" :: "l"(gen));
    }
}
__device__ __forceinline__ unsigned read_gen(unsigned* gen) {
    unsigned g;
    asm volatile("ld.acquire.gpu.u32 %0, [%1];" : "=r"(g) : "l"(gen));
    return g;
}

// pack one unit's hi/lo bf16 into the fragment buffer
__device__ __forceinline__ void pack_unit(char* bufbase, uint32_t off, float v) {
    __nv_bfloat16 h = __float2bfloat16(v);
    __nv_bfloat16 lo = __float2bfloat16(v - __bfloat162float(h));
    *(unsigned short*)(bufbase + off)       = __bfloat16_as_ushort(h);
    *(unsigned short*)(bufbase + off + 512) = __bfloat16_as_ushort(lo);
}

// ---- GEMM for one group: warp kq covers k-tiles [4kq,4kq+4), both batch-tiles ----
__device__ __forceinline__ void gemm_grp(uint32_t sbase, const uint4* gb, int kq,
                                         uint32_t boff4, uint32_t boff2,
                                         float acc[2][3][4]) {
    #pragma unroll
    for (int bt = 0; bt < 2; bt++)
        #pragma unroll
        for (int nt = 0; nt < 3; nt++)
            #pragma unroll
            for (int e = 0; e < 4; e++) acc[bt][nt][e] = 0.f;

    uint4 A[2][4];
    #pragma unroll
    for (int j = 0; j < 2; j++)
        #pragma unroll
        for (int i = 0; i < 4; i++)
            A[j][i] = __ldcg(gb + j * 128 + i * 32);

    #pragma unroll
    for (int kt = 0; kt < 4; kt++) {
        uint4 c0h = A[kt & 1][0], c0l = A[kt & 1][1];
        uint4 c1h = A[kt & 1][2], c1l = A[kt & 1][3];
        if (kt < 2) {
            #pragma unroll
            for (int i = 0; i < 4; i++)
                A[kt & 1][i] = __ldcg(gb + (kt + 2) * 128 + i * 32);
        }
        uint32_t wb = sbase + SM_W + (uint32_t)(kq * 4 + kt) * 32;
        uint32_t bh01[4], bl01[4], bh2[2], bl2[2];
        ldsm4(bh01, wb + boff4);
        ldsm2(bh2,  wb + 16 * W_NSTR + boff2);
        ldsm4(bl01, wb + W_PSTR + boff4);
        ldsm2(bl2,  wb + W_PSTR + 16 * W_NSTR + boff2);

        mma4(acc[0][0], c0h, bh01[0], bh01[1]);
        mma4(acc[0][1], c0h, bh01[2], bh01[3]);
        mma4(acc[0][2], c0h, bh2[0],  bh2[1]);
        mma4(acc[0][0], c0h, bl01[0], bl01[1]);
        mma4(acc[0][1], c0h, bl01[2], bl01[3]);
        mma4(acc[0][2], c0h, bl2[0],  bl2[1]);
        mma4(acc[0][0], c0l, bh01[0], bh01[1]);
        mma4(acc[0][1], c0l, bh01[2], bh01[3]);
        mma4(acc[0][2], c0l, bh2[0],  bh2[1]);

        mma4(acc[1][0], c1h, bh01[0], bh01[1]);
        mma4(acc[1][1], c1h, bh01[2], bh01[3]);
        mma4(acc[1][2], c1h, bh2[0],  bh2[1]);
        mma4(acc[1][0], c1h, bl01[0], bl01[1]);
        mma4(acc[1][1], c1h, bl01[2], bl01[3]);
        mma4(acc[1][2], c1h, bl2[0],  bl2[1]);
        mma4(acc[1][0], c1l, bh01[0], bh01[1]);
        mma4(acc[1][1], c1l, bh01[2], bh01[3]);
        mma4(acc[1][2], c1l, bh2[0],  bh2[1]);
    }
}

__device__ __forceinline__ void sts_planes(float* pl, float acc[2][3][4], int l) {
    int row = l >> 2, c2 = (l & 3) * 2;
    #pragma unroll
    for (int bt = 0; bt < 2; bt++) {
        int bb0 = bt * 16 + row;
        #pragma unroll
        for (int nt = 0; nt < 3; nt++) {
            int j0 = nt * 8 + c2;
            *(float2*)&pl[bb0 * 26 + j0]       = make_float2(acc[bt][nt][0], acc[bt][nt][1]);
            *(float2*)&pl[(bb0 + 8) * 26 + j0] = make_float2(acc[bt][nt][2], acc[bt][nt][3]);
        }
    }
}

__device__ __forceinline__ float gate_step(const float* rec, int gb, int uu,
                                           float az_in, float ar_in, float ah_in,
                                           float bz, float brr, float bhh, float hold) {
    float rz = bz, rr = brr, rh = bhh;
    #pragma unroll
    for (int p = 0; p < 16; p++) {
        const float* pl = rec + p * REC_PL + gb * 26;
        rz += pl[uu];
        rr += pl[8 + uu];
        rh += pl[16 + uu];
    }
    float z  = 1.f / (1.f + __expf(-(az_in + rz)));
    float r  = 1.f / (1.f + __expf(-(ar_in + rr)));
    float hh = tanhf(ah_in + r * rh);
    return z * hold + (1.f - z) * hh;
}

// ---- persistent GRU: two batch groups, pipelined barriers ----
__global__ void __launch_bounds__(NT, 1)
gru_all(const int* __restrict__ x, const float* __restrict__ hidden,
        const float* __restrict__ Win, const float* __restrict__ Wrec,
        const float* __restrict__ bin, const float* __restrict__ brec,
        float* __restrict__ out) {
    extern __shared__ __align__(1024) char smem[];
    const uint32_t sbase = smem_u32(smem);
    float* rec0 = (float*)(smem + SM_REC0);
    float* rec1 = (float*)(smem + SM_REC1);
    const int tid = threadIdx.x;
    const int wid = tid >> 5;
    const int l   = tid & 31;
    const int u0  = blockIdx.x * 8;

    // ---- one-time: W_rec slice -> bf16 hi/lo in SMEM [pass][n][k] ----
    for (int idx = tid; idx < 24 * U; idx += NT) {
        int k = idx / 24;
        int j = idx - k * 24;
        int gate = j >> 3, uu = j & 7;
        float w = Wrec[(size_t)k * G3 + gate * U + u0 + uu];
        __nv_bfloat16 hi = __float2bfloat16(w);
        __nv_bfloat16 lo = __float2bfloat16(w - __bfloat162float(hi));
        *(__nv_bfloat16*)(smem + SM_W + j * W_NSTR + k * 2) = hi;
        *(__nv_bfloat16*)(smem + SM_W + W_PSTR + j * W_NSTR + k * 2) = lo;
    }

    // ---- gate-thread setup (tid < 256): one unit per thread, per group ----
    const int gb = tid >> 3;           // batch within group 0..31
    const int uu = tid & 7;
    const int kk = u0 >> 4;
    const int klocal8 = u0 & 8;
    const int up = ((klocal8 + uu) >> 1) & 3;
    const int r_ = gb & 15, btg = gb >> 4;
    const uint32_t woff = (uint32_t)((r_ & 7) * 4 + up) * 16
                        + (uint32_t)((r_ >> 3) + 2 * (klocal8 >> 3)) * 4
                        + (uu & 1) * 2;
    const uint32_t off_g0 = (uint32_t)((kk * 4) + btg * 2) * 512 + woff;
    const uint32_t off_g1 = (uint32_t)(((64 + kk) * 4) + btg * 2) * 512 + woff;

    float biz = 0, bir = 0, bih = 0, bz = 0, brr = 0, bhh = 0;
    float hold0 = 0, hold1 = 0;
    int tok0 = 0, tok1 = 0;
    if (tid < 256) {
        biz = bin[0 * U + u0 + uu]; bir = bin[1 * U + u0 + uu]; bih = bin[2 * U + u0 + uu];
        bz  = brec[0 * U + u0 + uu]; brr = brec[1 * U + u0 + uu]; bhh = brec[2 * U + u0 + uu];
        hold0 = hidden[(size_t)gb * U + u0 + uu];
        hold1 = hidden[(size_t)(32 + gb) * U + u0 + uu];
        pack_unit((char*)g_hpk[0], off_g0, hold0);
        pack_unit((char*)g_hpk[0], off_g1, hold1);
        tok0 = x[gb * T];
        tok1 = x[(32 + gb) * T];
    }
    unsigned tgt0 = read_gen(&g_gen0);
    unsigned tgt1 = read_gen(&g_gen1);
    __syncthreads();
    if (tid == 0) { arrive_bar(&g_cnt0, &g_gen0); arrive_bar(&g_cnt1, &g_gen1); }

    // ---- warp MMA mapping ----
    const int kq = wid;
    const uint32_t boff4 = (uint32_t)((l >> 4) * 8 + (l & 7)) * W_NSTR + ((l >> 3) & 1) * 16;
    const uint32_t boff2 = (uint32_t)(l & 7) * W_NSTR + (l & 8) * 2;

    for (int t = 0; t < T; t++) {
        const int par = t & 1;

        // -------- group 0 --------
        float xz0 = 0, xr0 = 0, xh0 = 0; int tn0 = 0;
        if (tid < 256) {
            const float* wrow = Win + (size_t)tok0 * G3 + u0 + uu;
            xz0 = wrow[0]; xr0 = wrow[U]; xh0 = wrow[2 * U];
            tn0 = (t + 1 < T) ? x[gb * T + t + 1] : 0;
        }
        tgt0++;
        wait_gen(&g_gen0, tgt0);
        {
            float acc[2][3][4];
            const uint4* gbp = g_hpk[par] + (size_t)(kq * 4) * 128 + l;
            gemm_grp(sbase, gbp, kq, boff4, boff2, acc);
            sts_planes(rec0 + kq * REC_PL, acc, l);
        }
        __syncthreads();
        if (tid < 256) {
            float hn = gate_step(rec0, gb, uu, xz0 + biz, xr0 + bir, xh0 + bih,
                                 bz, brr, bhh, hold0);
            hold0 = hn;
            out[((size_t)gb * T + t) * U + u0 + uu] = hn;
            if (t == T - 1)
                out[(size_t)B * T * U + (size_t)gb * U + u0 + uu] = hn;
            pack_unit((char*)g_hpk[par ^ 1], off_g0, hn);
            tok0 = tn0;
            asm volatile("bar.sync 1, 256;" ::: "memory");
            if (tid == 0) arrive_bar(&g_cnt0, &g_gen0);
        }

        // -------- group 1 --------
        float xz1 = 0, xr1 = 0, xh1 = 0; int tn1 = 0;
        if (tid < 256) {
            const float* wrow = Win + (size_t)tok1 * G3 + u0 + uu;
            xz1 = wrow[0]; xr1 = wrow[U]; xh1 = wrow[2 * U];
            tn1 = (t + 1 < T) ? x[(32 + gb) * T + t + 1] : 0;
        }
        tgt1++;
        wait_gen(&g_gen1, tgt1);
        {
            float acc[2][3][4];
            const uint4* gbp = g_hpk[par] + (size_t)((64 + kq * 4)) * 128 + l;
            gemm_grp(sbase, gbp, kq, boff4, boff2, acc);
            sts_planes(rec1 + kq * REC_PL, acc, l);
        }
        __syncthreads();
        if (tid < 256) {
            float hn = gate_step(rec1, gb, uu, xz1 + biz, xr1 + bir, xh1 + bih,
                                 bz, brr, bhh, hold1);
            hold1 = hn;
            out[((size_t)(32 + gb) * T + t) * U + u0 + uu] = hn;
            if (t == T - 1)
                out[(size_t)B * T * U + (size_t)(32 + gb) * U + u0 + uu] = hn;
            pack_unit((char*)g_hpk[par ^ 1], off_g1, hn);
            tok1 = tn1;
            asm volatile("bar.sync 1, 256;" ::: "memory");
            if (tid == 0) arrive_bar(&g_cnt1, &g_gen1);
        }
    }
}

extern "C" void kernel_launch(void* const* d_in, const int* in_sizes, int n_in,
                              void* d_out, int out_size) {
    const int*   x      = (const int*)d_in[0];
    const float* hidden = (const float*)d_in[1];
    const float* Win    = (const float*)d_in[2];
    const float* Wrec   = (const float*)d_in[3];
    const float* bin    = (const float*)d_in[4];
    const float* brec   = (const float*)d_in[5];
    float* out = (float*)d_out;

    cudaFuncSetAttribute(gru_all, cudaFuncAttributeMaxDynamicSharedMemorySize, SMEM_TOTAL);
    gru_all<<<NBLK, NT, SMEM_TOTAL>>>(x, hidden, Win, Wrec, bin, brec, out);
}

// round 9
// speedup vs baseline: 1.3247x; 1.3247x over previous
#include <cuda_runtime.h>
#include <cuda_bf16.h>
#include <cstdint>
#include <math.h>

#define B     64
#define T     256
#define U     1024
#define G3    3072
#define NBLK  128
#define NT    512

// h packed in MMA A-fragment order (round-7 layout, verified):
// [par][ ((bt*64 + kk)*2 + half)*32 + lane ] -> uint4
__device__ __align__(16) uint4 g_hpk[2][4 * 64 * 2 * 32];
__device__ unsigned g_flag[8];          // per k-eighth dependency counters (monotonic)
__device__ unsigned g_bar_cnt, g_bar_gen;

// ---- SMEM layout (bytes) ----
#define SM_W     0
#define W_NSTR   2064
#define W_PSTR   49536
#define SM_REC   99072              // float [8 plane][64][26]
#define REC_PL   1664               // floats per plane
#define SMEM_TOTAL (99072 + 8*6656) // 152320

// ---- PTX helpers ----
__device__ __forceinline__ uint32_t smem_u32(const void* p) {
    uint32_t a;
    asm("{ .reg .u64 t; cvta.to.shared.u64 t, %1; cvt.u32.u64 %0, t; }" : "=r"(a) : "l"(p));
    return a;
}
__device__ __forceinline__ void ldsm2(uint32_t* r, uint32_t addr) {
    asm volatile("ldmatrix.sync.aligned.m8n8.x2.shared.b16 {%0,%1}, [%2];"
                 : "=r"(r[0]), "=r"(r[1]) : "r"(addr));
}
__device__ __forceinline__ void ldsm4(uint32_t* r, uint32_t addr) {
    asm volatile("ldmatrix.sync.aligned.m8n8.x4.shared.b16 {%0,%1,%2,%3}, [%4];"
                 : "=r"(r[0]), "=r"(r[1]), "=r"(r[2]), "=r"(r[3]) : "r"(addr));
}
__device__ __forceinline__ void mma4(float* c, const uint4& a, uint32_t b0, uint32_t b1) {
    asm volatile("mma.sync.aligned.m16n8k16.row.col.f32.bf16.bf16.f32 "
                 "{%0,%1,%2,%3}, {%4,%5,%6,%7}, {%8,%9}, {%0,%1,%2,%3};"
                 : "+f"(c[0]), "+f"(c[1]), "+f"(c[2]), "+f"(c[3])
                 : "r"(a.x), "r"(a.y), "r"(a.z), "r"(a.w), "r"(b0), "r"(b1));
}
__device__ __forceinline__ void wait_flag(unsigned* f, unsigned tgt) {
    unsigned g;
    while (1) {
        asm volatile("ld.acquire.gpu.u32 %0, [%1];" : "=r"(g) : "l"(f));
        if ((int)(g - tgt) >= 0) break;
        __nanosleep(32);
    }
}
__device__ __forceinline__ void acq_flag(unsigned* f) {
    unsigned g;
    asm volatile("ld.acquire.gpu.u32 %0, [%1];" : "=r"(g) : "l"(f));
    (void)g;
}
__device__ __forceinline__ void arrive_flag(unsigned* f) {
    asm volatile("red.release.gpu.global.add.u32 [%0], 1;" :: "l"(f));
}

// startup-only grid barrier
__device__ __forceinline__ void grid_barrier() {
    __syncthreads();
    if (threadIdx.x == 0) {
        unsigned gen0;
        asm volatile("ld.acquire.gpu.u32 %0, [%1];" : "=r"(gen0) : "l"(&g_bar_gen));
        unsigned prev;
        asm volatile("atom.release.gpu.global.add.u32 %0, [%1], 1;" : "=r"(prev) : "l"(&g_bar_cnt));
        if (prev == NBLK - 1) {
            asm volatile("st.relaxed.gpu.global.u32 [%0], 0;" :: "l"(&g_bar_cnt));
            asm volatile("red.release.gpu.global.add.u32 [%0], 1;" :: "l"(&g_bar_gen));
        } else {
            unsigned g;
            do { asm volatile("ld.acquire.gpu.u32 %0, [%1];" : "=r"(g) : "l"(&g_bar_gen)); } while (g == gen0);
        }
    }
    __syncthreads();
}

// pack one unit (b, u0+uu): hi at off, lo at off+512
__device__ __forceinline__ void pack_unit(char* bufbase, uint32_t off, float v) {
    __nv_bfloat16 h = __float2bfloat16(v);
    __nv_bfloat16 lo = __float2bfloat16(v - __bfloat162float(h));
    *(unsigned short*)(bufbase + off)       = __bfloat16_as_ushort(h);
    *(unsigned short*)(bufbase + off + 512) = __bfloat16_as_ushort(lo);
}

__global__ void __launch_bounds__(NT, 1)
gru_all(const int* __restrict__ x, const float* __restrict__ hidden,
        const float* __restrict__ Win, const float* __restrict__ Wrec,
        const float* __restrict__ bin, const float* __restrict__ brec,
        float* __restrict__ out) {
    extern __shared__ __align__(1024) char smem[];
    const uint32_t sbase = smem_u32(smem);
    float* rec_s = (float*)(smem + SM_REC);
    const int tid = threadIdx.x;
    const int wid = tid >> 5;
    const int l   = tid & 31;
    const int blk = blockIdx.x;
    const int u0  = blk * 8;

    // ---- one-time: W_rec slice -> bf16 hi/lo in SMEM [pass][n][k] ----
    for (int idx = tid; idx < 24 * U; idx += NT) {
        int k = idx / 24;
        int j = idx - k * 24;
        int gate = j >> 3, uu = j & 7;
        float w = Wrec[(size_t)k * G3 + gate * U + u0 + uu];
        __nv_bfloat16 hi = __float2bfloat16(w);
        __nv_bfloat16 lo = __float2bfloat16(w - __bfloat162float(hi));
        *(__nv_bfloat16*)(smem + SM_W + j * W_NSTR + k * 2) = hi;
        *(__nv_bfloat16*)(smem + SM_W + W_PSTR + j * W_NSTR + k * 2) = lo;
    }

    // ---- gate mapping: all 512 threads, 1 unit each: (b, uu) ----
    const int b  = tid >> 3;
    const int uu = tid & 7;
    const int btg = b >> 4, r_ = b & 15;
    const int kk_self = u0 >> 4;
    const uint32_t woff = (uint32_t)((r_ & 7) * 4 + ((uu >> 1) & 3)) * 16
                        + (uint32_t)((r_ >> 3) + 2 * ((u0 >> 3) & 1)) * 4
                        + (uu & 1) * 2;
    const uint32_t poff = (uint32_t)((btg * 64 + kk_self) * 2) * 512 + woff;

    const float biz = bin[0 * U + u0 + uu];
    const float bir = bin[1 * U + u0 + uu];
    const float bih = bin[2 * U + u0 + uu];
    const float bz  = brec[0 * U + u0 + uu];
    const float brr = brec[1 * U + u0 + uu];
    const float bhh = brec[2 * U + u0 + uu];
    float hold = hidden[(size_t)b * U + u0 + uu];
    int tok = x[b * T];

    // ---- warp MMA mapping: kq = wid>>1 (k-eighth), bth = wid&1 (batch half) ----
    const int kq  = wid >> 1;
    const int bth = wid & 1;
    const uint32_t boff4 = (uint32_t)((l >> 4) * 8 + (l & 7)) * W_NSTR + ((l >> 3) & 1) * 16;
    const uint32_t boff2 = (uint32_t)(l & 7) * W_NSTR + (l & 8) * 2;
    const int grp = blk >> 4;   // this CTA's producer flag group

    // capture flag base BEFORE anyone arrives (grid barrier orders this)
    unsigned fbase = *(volatile unsigned*)&g_flag[kq];
    grid_barrier();

    // publish h0 into buffer 0
    pack_unit((char*)g_hpk[0], poff, hold);
    __syncthreads();
    if (tid == 0) arrive_flag(&g_flag[grp]);

    for (int t = 0; t < T; t++) {
        const int par = t & 1;

        // gate-input loads issued before the flag wait (latency overlap)
        const float* wrow = Win + (size_t)tok * G3 + u0 + uu;
        float xz = wrow[0], xr = wrow[U], xh = wrow[2 * U];
        int tok_n = (t + 1 < T) ? x[b * T + t + 1] : 0;

        // wait for the 16 producer CTAs of this warp's k-eighth
        if (l == 0) wait_flag(&g_flag[kq], fbase + 16u * (t + 1));
        __syncwarp();
        acq_flag(&g_flag[kq]);   // acquire on every lane

        // ---- GEMM: 8 k-tiles, 2 batch-tiles (bt = 2*bth, 2*bth+1) ----
        float acc[2][3][4];
        #pragma unroll
        for (int bt = 0; bt < 2; bt++)
            #pragma unroll
            for (int nt = 0; nt < 3; nt++)
                #pragma unroll
                for (int e = 0; e < 4; e++) acc[bt][nt][e] = 0.f;

        const uint4* pA0 = g_hpk[par] + (size_t)(((2 * bth)     * 64 + kq * 8) * 2) * 32 + l;
        const uint4* pA1 = g_hpk[par] + (size_t)(((2 * bth + 1) * 64 + kq * 8) * 2) * 32 + l;

        uint4 Ah[2][2], Al[2][2];
        #pragma unroll
        for (int i = 0; i < 2; i++) {
            Ah[0][i] = __ldcg(pA0 + i * 64); Al[0][i] = __ldcg(pA0 + i * 64 + 32);
            Ah[1][i] = __ldcg(pA1 + i * 64); Al[1][i] = __ldcg(pA1 + i * 64 + 32);
        }

        #pragma unroll
        for (int kt = 0; kt < 8; kt++) {
            uint32_t wb = sbase + SM_W + (uint32_t)(kq * 8 + kt) * 32;
            uint32_t bh01[4], bl01[4], bh2[2], bl2[2];
            ldsm4(bh01, wb + boff4);
            ldsm2(bh2,  wb + 16 * W_NSTR + boff2);
            ldsm4(bl01, wb + W_PSTR + boff4);
            ldsm2(bl2,  wb + W_PSTR + 16 * W_NSTR + boff2);

            uint4 c0h = Ah[0][kt & 1], c0l = Al[0][kt & 1];
            uint4 c1h = Ah[1][kt & 1], c1l = Al[1][kt & 1];
            if (kt < 6) {
                Ah[0][kt & 1] = __ldcg(pA0 + (kt + 2) * 64);
                Al[0][kt & 1] = __ldcg(pA0 + (kt + 2) * 64 + 32);
                Ah[1][kt & 1] = __ldcg(pA1 + (kt + 2) * 64);
                Al[1][kt & 1] = __ldcg(pA1 + (kt + 2) * 64 + 32);
            }

            mma4(acc[0][0], c0h, bh01[0], bh01[1]);
            mma4(acc[0][1], c0h, bh01[2], bh01[3]);
            mma4(acc[0][2], c0h, bh2[0],  bh2[1]);
            mma4(acc[0][0], c0h, bl01[0], bl01[1]);
            mma4(acc[0][1], c0h, bl01[2], bl01[3]);
            mma4(acc[0][2], c0h, bl2[0],  bl2[1]);
            mma4(acc[0][0], c0l, bh01[0], bh01[1]);
            mma4(acc[0][1], c0l, bh01[2], bh01[3]);
            mma4(acc[0][2], c0l, bh2[0],  bh2[1]);

            mma4(acc[1][0], c1h, bh01[0], bh01[1]);
            mma4(acc[1][1], c1h, bh01[2], bh01[3]);
            mma4(acc[1][2], c1h, bh2[0],  bh2[1]);
            mma4(acc[1][0], c1h, bl01[0], bl01[1]);
            mma4(acc[1][1], c1h, bl01[2], bl01[3]);
            mma4(acc[1][2], c1h, bl2[0],  bl2[1]);
            mma4(acc[1][0], c1l, bh01[0], bh01[1]);
            mma4(acc[1][1], c1l, bh01[2], bh01[3]);
            mma4(acc[1][2], c1l, bh2[0],  bh2[1]);
        }

        // ---- epilogue: partials -> plane kq, rows [32*bth, 32*bth+32) ----
        {
            float* pl = rec_s + kq * REC_PL;
            int row = l >> 2, c2 = (l & 3) * 2;
            #pragma unroll
            for (int bt = 0; bt < 2; bt++) {
                int bb0 = (2 * bth + bt) * 16 + row;
                #pragma unroll
                for (int nt = 0; nt < 3; nt++) {
                    int j0 = nt * 8 + c2;
                    *(float2*)&pl[bb0 * 26 + j0]       = make_float2(acc[bt][nt][0], acc[bt][nt][1]);
                    *(float2*)&pl[(bb0 + 8) * 26 + j0] = make_float2(acc[bt][nt][2], acc[bt][nt][3]);
                }
            }
        }
        __syncthreads();

        // ---- gates: every thread, 1 unit ----
        {
            float rz = bz, rr = brr, rh = bhh;
            #pragma unroll
            for (int p = 0; p < 8; p++) {
                const float* pl = rec_s + p * REC_PL + b * 26;
                rz += pl[uu];
                rr += pl[8 + uu];
                rh += pl[16 + uu];
            }
            float z  = 1.f / (1.f + __expf(-(xz + biz + rz)));
            float r  = 1.f / (1.f + __expf(-(xr + bir + rr)));
            float hh = tanhf(xh + bih + r * rh);
            float hn = z * hold + (1.f - z) * hh;
            hold = hn;
            pack_unit((char*)g_hpk[par ^ 1], poff, hn);
            __syncthreads();
            if (tid == 0 && t < T - 1) arrive_flag(&g_flag[grp]);
            out[((size_t)b * T + t) * U + u0 + uu] = hn;
            if (t == T - 1)
                out[(size_t)B * T * U + (size_t)b * U + u0 + uu] = hn;
            tok = tok_n;
        }
    }
}

extern "C" void kernel_launch(void* const* d_in, const int* in_sizes, int n_in,
                              void* d_out, int out_size) {
    const int*   x      = (const int*)d_in[0];
    const float* hidden = (const float*)d_in[1];
    const float* Win    = (const float*)d_in[2];
    const float* Wrec   = (const float*)d_in[3];
    const float* bin    = (const float*)d_in[4];
    const float* brec   = (const float*)d_in[5];
    float* out = (float*)d_out;

    cudaFuncSetAttribute(gru_all, cudaFuncAttributeMaxDynamicSharedMemorySize, SMEM_TOTAL);
    gru_all<<<NBLK, NT, SMEM_TOTAL>>>(x, hidden, Win, Wrec, bin, brec, out);
}

// round 10
// speedup vs baseline: 1.3314x; 1.0051x over previous
#include <cuda_runtime.h>
#include <cuda_bf16.h>
#include <cstdint>
#include <math.h>

#define B     64
#define T     256
#define U     1024
#define G3    3072
#define NBLK  128
#define NT    512

// h packed in MMA A-fragment order (round-7 layout, verified):
// [par][ ((bt*64 + kk)*2 + half)*32 + lane ] -> uint4
__device__ __align__(16) uint4 g_hpk[2][4 * 64 * 2 * 32];
__device__ unsigned g_flag[8];          // per k-eighth dependency counters (monotonic)
__device__ unsigned g_bar_cnt, g_bar_gen;

// ---- SMEM layout (bytes) ----
#define SM_W     0
#define W_NSTR   2064
#define W_PSTR   49536
#define SM_REC   99072              // float [8 plane][64][26]
#define REC_PL   1664               // floats per plane
#define SMEM_TOTAL (99072 + 8*6656) // 152320

// ---- PTX helpers ----
__device__ __forceinline__ uint32_t smem_u32(const void* p) {
    uint32_t a;
    asm("{ .reg .u64 t; cvta.to.shared.u64 t, %1; cvt.u32.u64 %0, t; }" : "=r"(a) : "l"(p));
    return a;
}
__device__ __forceinline__ void ldsm2(uint32_t* r, uint32_t addr) {
    asm volatile("ldmatrix.sync.aligned.m8n8.x2.shared.b16 {%0,%1}, [%2];"
                 : "=r"(r[0]), "=r"(r[1]) : "r"(addr));
}
__device__ __forceinline__ void ldsm4(uint32_t* r, uint32_t addr) {
    asm volatile("ldmatrix.sync.aligned.m8n8.x4.shared.b16 {%0,%1,%2,%3}, [%4];"
                 : "=r"(r[0]), "=r"(r[1]), "=r"(r[2]), "=r"(r[3]) : "r"(addr));
}
__device__ __forceinline__ void mma4(float* c, const uint4& a, uint32_t b0, uint32_t b1) {
    asm volatile("mma.sync.aligned.m16n8k16.row.col.f32.bf16.bf16.f32 "
                 "{%0,%1,%2,%3}, {%4,%5,%6,%7}, {%8,%9}, {%0,%1,%2,%3};"
                 : "+f"(c[0]), "+f"(c[1]), "+f"(c[2]), "+f"(c[3])
                 : "r"(a.x), "r"(a.y), "r"(a.z), "r"(a.w), "r"(b0), "r"(b1));
}
__device__ __forceinline__ void wait_flag(unsigned* f, unsigned tgt) {
    unsigned g;
    while (1) {
        asm volatile("ld.acquire.gpu.u32 %0, [%1];" : "=r"(g) : "l"(f));
        if ((int)(g - tgt) >= 0) break;
        __nanosleep(32);
    }
}
__device__ __forceinline__ void acq_flag(unsigned* f) {
    unsigned g;
    asm volatile("ld.acquire.gpu.u32 %0, [%1];" : "=r"(g) : "l"(f));
    (void)g;
}
__device__ __forceinline__ void arrive_flag(unsigned* f) {
    asm volatile("red.release.gpu.global.add.u32 [%0], 1;" :: "l"(f));
}

// startup-only grid barrier
__device__ __forceinline__ void grid_barrier() {
    __syncthreads();
    if (threadIdx.x == 0) {
        unsigned gen0;
        asm volatile("ld.acquire.gpu.u32 %0, [%1];" : "=r"(gen0) : "l"(&g_bar_gen));
        unsigned prev;
        asm volatile("atom.release.gpu.global.add.u32 %0, [%1], 1;" : "=r"(prev) : "l"(&g_bar_cnt));
        if (prev == NBLK - 1) {
            asm volatile("st.relaxed.gpu.global.u32 [%0], 0;" :: "l"(&g_bar_cnt));
            asm volatile("red.release.gpu.global.add.u32 [%0], 1;" :: "l"(&g_bar_gen));
        } else {
            unsigned g;
            do { asm volatile("ld.acquire.gpu.u32 %0, [%1];" : "=r"(g) : "l"(&g_bar_gen)); } while (g == gen0);
        }
    }
    __syncthreads();
}

// pack one unit (b, u0+uu): hi at off, lo at off+512
__device__ __forceinline__ void pack_unit(char* bufbase, uint32_t off, float v) {
    __nv_bfloat16 h = __float2bfloat16(v);
    __nv_bfloat16 lo = __float2bfloat16(v - __bfloat162float(h));
    *(unsigned short*)(bufbase + off)       = __bfloat16_as_ushort(h);
    *(unsigned short*)(bufbase + off + 512) = __bfloat16_as_ushort(lo);
}

__global__ void __launch_bounds__(NT, 1)
gru_all(const int* __restrict__ x, const float* __restrict__ hidden,
        const float* __restrict__ Win, const float* __restrict__ Wrec,
        const float* __restrict__ bin, const float* __restrict__ brec,
        float* __restrict__ out) {
    extern __shared__ __align__(1024) char smem[];
    const uint32_t sbase = smem_u32(smem);
    float* rec_s = (float*)(smem + SM_REC);
    const int tid = threadIdx.x;
    const int wid = tid >> 5;
    const int l   = tid & 31;
    const int blk = blockIdx.x;
    const int u0  = blk * 8;

    // ---- one-time: W_rec slice -> bf16 hi/lo in SMEM [pass][n][k] ----
    for (int idx = tid; idx < 24 * U; idx += NT) {
        int k = idx / 24;
        int j = idx - k * 24;
        int gate = j >> 3, uu = j & 7;
        float w = Wrec[(size_t)k * G3 + gate * U + u0 + uu];
        __nv_bfloat16 hi = __float2bfloat16(w);
        __nv_bfloat16 lo = __float2bfloat16(w - __bfloat162float(hi));
        *(__nv_bfloat16*)(smem + SM_W + j * W_NSTR + k * 2) = hi;
        *(__nv_bfloat16*)(smem + SM_W + W_PSTR + j * W_NSTR + k * 2) = lo;
    }

    // ---- gate mapping: all 512 threads, 1 unit each: (b, uu) ----
    const int b  = tid >> 3;
    const int uu = tid & 7;
    const int btg = b >> 4, r_ = b & 15;
    const int kk_self = u0 >> 4;
    const uint32_t woff = (uint32_t)((r_ & 7) * 4 + ((uu >> 1) & 3)) * 16
                        + (uint32_t)((r_ >> 3) + 2 * ((u0 >> 3) & 1)) * 4
                        + (uu & 1) * 2;
    const uint32_t poff = (uint32_t)((btg * 64 + kk_self) * 2) * 512 + woff;

    const float biz = bin[0 * U + u0 + uu];
    const float bir = bin[1 * U + u0 + uu];
    const float bih = bin[2 * U + u0 + uu];
    const float bz  = brec[0 * U + u0 + uu];
    const float brr = brec[1 * U + u0 + uu];
    const float bhh = brec[2 * U + u0 + uu];
    float hold = hidden[(size_t)b * U + u0 + uu];
    int tok = x[b * T];

    // ---- warp MMA mapping: kq = wid>>1 (k-eighth), bth = wid&1 (batch half) ----
    const int kq  = wid >> 1;
    const int bth = wid & 1;
    const uint32_t boff4 = (uint32_t)((l >> 4) * 8 + (l & 7)) * W_NSTR + ((l >> 3) & 1) * 16;
    const uint32_t boff2 = (uint32_t)(l & 7) * W_NSTR + (l & 8) * 2;
    const int grp = blk >> 4;   // this CTA's producer flag group

    // capture flag base BEFORE anyone arrives (grid barrier orders this)
    unsigned fbase = *(volatile unsigned*)&g_flag[kq];
    grid_barrier();

    // publish h0 into buffer 0
    pack_unit((char*)g_hpk[0], poff, hold);
    __syncthreads();
    if (tid == 0) arrive_flag(&g_flag[grp]);

    for (int t = 0; t < T; t++) {
        const int par = t & 1;

        // gate-input loads issued before the flag wait (latency overlap)
        const float* wrow = Win + (size_t)tok * G3 + u0 + uu;
        float xz = wrow[0], xr = wrow[U], xh = wrow[2 * U];
        int tok_n = (t + 1 < T) ? x[b * T + t + 1] : 0;

        // wait for the 16 producer CTAs of this warp's k-eighth
        if (l == 0) wait_flag(&g_flag[kq], fbase + 16u * (t + 1));
        __syncwarp();
        acq_flag(&g_flag[kq]);   // acquire on every lane

        // ---- GEMM: 8 k-tiles, 2 batch-tiles (bt = 2*bth, 2*bth+1) ----
        float acc[2][3][4];
        #pragma unroll
        for (int bt = 0; bt < 2; bt++)
            #pragma unroll
            for (int nt = 0; nt < 3; nt++)
                #pragma unroll
                for (int e = 0; e < 4; e++) acc[bt][nt][e] = 0.f;

        const uint4* pA0 = g_hpk[par] + (size_t)(((2 * bth)     * 64 + kq * 8) * 2) * 32 + l;
        const uint4* pA1 = g_hpk[par] + (size_t)(((2 * bth + 1) * 64 + kq * 8) * 2) * 32 + l;

        uint4 Ah[2][2], Al[2][2];
        #pragma unroll
        for (int i = 0; i < 2; i++) {
            Ah[0][i] = __ldcg(pA0 + i * 64); Al[0][i] = __ldcg(pA0 + i * 64 + 32);
            Ah[1][i] = __ldcg(pA1 + i * 64); Al[1][i] = __ldcg(pA1 + i * 64 + 32);
        }

        #pragma unroll
        for (int kt = 0; kt < 8; kt++) {
            uint32_t wb = sbase + SM_W + (uint32_t)(kq * 8 + kt) * 32;
            uint32_t bh01[4], bl01[4], bh2[2], bl2[2];
            ldsm4(bh01, wb + boff4);
            ldsm2(bh2,  wb + 16 * W_NSTR + boff2);
            ldsm4(bl01, wb + W_PSTR + boff4);
            ldsm2(bl2,  wb + W_PSTR + 16 * W_NSTR + boff2);

            uint4 c0h = Ah[0][kt & 1], c0l = Al[0][kt & 1];
            uint4 c1h = Ah[1][kt & 1], c1l = Al[1][kt & 1];
            if (kt < 6) {
                Ah[0][kt & 1] = __ldcg(pA0 + (kt + 2) * 64);
                Al[0][kt & 1] = __ldcg(pA0 + (kt + 2) * 64 + 32);
                Ah[1][kt & 1] = __ldcg(pA1 + (kt + 2) * 64);
                Al[1][kt & 1] = __ldcg(pA1 + (kt + 2) * 64 + 32);
            }

            mma4(acc[0][0], c0h, bh01[0], bh01[1]);
            mma4(acc[0][1], c0h, bh01[2], bh01[3]);
            mma4(acc[0][2], c0h, bh2[0],  bh2[1]);
            mma4(acc[0][0], c0h, bl01[0], bl01[1]);
            mma4(acc[0][1], c0h, bl01[2], bl01[3]);
            mma4(acc[0][2], c0h, bl2[0],  bl2[1]);
            mma4(acc[0][0], c0l, bh01[0], bh01[1]);
            mma4(acc[0][1], c0l, bh01[2], bh01[3]);
            mma4(acc[0][2], c0l, bh2[0],  bh2[1]);

            mma4(acc[1][0], c1h, bh01[0], bh01[1]);
            mma4(acc[1][1], c1h, bh01[2], bh01[3]);
            mma4(acc[1][2], c1h, bh2[0],  bh2[1]);
            mma4(acc[1][0], c1h, bl01[0], bl01[1]);
            mma4(acc[1][1], c1h, bl01[2], bl01[3]);
            mma4(acc[1][2], c1h, bl2[0],  bl2[1]);
            mma4(acc[1][0], c1l, bh01[0], bh01[1]);
            mma4(acc[1][1], c1l, bh01[2], bh01[3]);
            mma4(acc[1][2], c1l, bh2[0],  bh2[1]);
        }

        // ---- epilogue: partials -> plane kq, rows [32*bth, 32*bth+32) ----
        {
            float* pl = rec_s + kq * REC_PL;
            int row = l >> 2, c2 = (l & 3) * 2;
            #pragma unroll
            for (int bt = 0; bt < 2; bt++) {
                int bb0 = (2 * bth + bt) * 16 + row;
                #pragma unroll
                for (int nt = 0; nt < 3; nt++) {
                    int j0 = nt * 8 + c2;
                    *(float2*)&pl[bb0 * 26 + j0]       = make_float2(acc[bt][nt][0], acc[bt][nt][1]);
                    *(float2*)&pl[(bb0 + 8) * 26 + j0] = make_float2(acc[bt][nt][2], acc[bt][nt][3]);
                }
            }
        }
        __syncthreads();

        // ---- gates: every thread, 1 unit ----
        {
            float rz = bz, rr = brr, rh = bhh;
            #pragma unroll
            for (int p = 0; p < 8; p++) {
                const float* pl = rec_s + p * REC_PL + b * 26;
                rz += pl[uu];
                rr += pl[8 + uu];
                rh += pl[16 + uu];
            }
            float z  = 1.f / (1.f + __expf(-(xz + biz + rz)));
            float r  = 1.f / (1.f + __expf(-(xr + bir + rr)));
            float hh = tanhf(xh + bih + r * rh);
            float hn = z * hold + (1.f - z) * hh;
            hold = hn;
            pack_unit((char*)g_hpk[par ^ 1], poff, hn);
            __syncthreads();
            if (tid == 0 && t < T - 1) arrive_flag(&g_flag[grp]);
            out[((size_t)b * T + t) * U + u0 + uu] = hn;
            if (t == T - 1)
                out[(size_t)B * T * U + (size_t)b * U + u0 + uu] = hn;
            tok = tok_n;
        }
    }
}

extern "C" void kernel_launch(void* const* d_in, const int* in_sizes, int n_in,
                              void* d_out, int out_size) {
    const int*   x      = (const int*)d_in[0];
    const float* hidden = (const float*)d_in[1];
    const float* Win    = (const float*)d_in[2];
    const float* Wrec   = (const float*)d_in[3];
    const float* bin    = (const float*)d_in[4];
    const float* brec   = (const float*)d_in[5];
    float* out = (float*)d_out;

    cudaFuncSetAttribute(gru_all, cudaFuncAttributeMaxDynamicSharedMemorySize, SMEM_TOTAL);
    gru_all<<<NBLK, NT, SMEM_TOTAL>>>(x, hidden, Win, Wrec, bin, brec, out);
}